// round 5
// baseline (speedup 1.0000x reference)
#include <cuda_runtime.h>
#include <cstdint>

#define BB 32
#define AA 8400
#define NCH 84
#define NCC 80
#define KTOP 1500
#define TPAD 1536
#define SORTN 2048
#define MAXDET 300
#define NW 47
#define NWP 48
#define CAP 384

// ---------------- device scratch (static, allocation-free) ----------------
__device__ uint64_t g_keys[BB * AA];
__device__ uint32_t g_cand[2][BB][AA];
__device__ float4   g_selbox[BB * TPAD];
__device__ float4   g_nmsbox[BB * TPAD];
__device__ float    g_selscore[BB * TPAD];
__device__ float    g_selcls[BB * TPAD];
__device__ uint8_t  g_clsSel[BB * TPAD];
__device__ uint32_t g_validbits[BB * NWP];

__device__ __forceinline__ uint32_t f2o(float f) {
    uint32_t u = __float_as_uint(f);
    return (u & 0x80000000u) ? ~u : (u | 0x80000000u);
}
__device__ __forceinline__ float o2f(uint32_t u) {
    return (u & 0x80000000u) ? __uint_as_float(u & 0x7FFFFFFFu)
                             : __uint_as_float(~u);
}

// bitonic compare-exchange via full-mask shfl (element index i, stage kk, dist j<32)
__device__ __forceinline__ uint64_t bshfl(uint64_t v, int i, int kk, int j) {
    uint64_t p = __shfl_xor_sync(0xFFFFFFFFu, v, j);
    bool up = (i & j) == 0;
    bool desc = (i & kk) == 0;
    bool takemax = (up == desc);
    return ((v > p) == takemax) ? v : p;
}

// ---------------- stage 1: score max/argmax -> packed keys ----------------
// key = f2o(masked_score) << 32 | (AA-1-a) << 7 | cls
// (index above class bits preserves exact top_k tie order: lower index first)
__global__ void k_score(const float* __restrict__ pred) {
    int q = blockIdx.x * blockDim.x + threadIdx.x;   // group of 4 anchors
    int b = blockIdx.y;
    const int Q = AA / 4;
    if (q >= Q) return;

    const float4* p4 = (const float4*)pred;
    size_t rowbase = ((size_t)b * NCH + 4) * Q + q;

    float4 best = p4[rowbase];
    int cx = 0, cy = 0, cz = 0, cw = 0;
#pragma unroll 8
    for (int c = 1; c < NCC; c++) {
        float4 v = p4[rowbase + (size_t)c * Q];
        if (v.x > best.x) { best.x = v.x; cx = c; }
        if (v.y > best.y) { best.y = v.y; cy = c; }
        if (v.z > best.z) { best.z = v.z; cz = c; }
        if (v.w > best.w) { best.w = v.w; cw = c; }
    }
    int a0 = q * 4;
    float sc[4] = {best.x, best.y, best.z, best.w};
    int   cl[4] = {cx, cy, cz, cw};
#pragma unroll
    for (int t = 0; t < 4; t++) {
        int a = a0 + t;
        float msc = (sc[t] > 0.25f) ? sc[t] : -1.0f;
        uint32_t lo = ((uint32_t)(AA - 1 - a) << 7) | (uint32_t)cl[t];
        g_keys[b * AA + a] = ((uint64_t)f2o(msc) << 32) | lo;
    }
}

// ---------------- stage 2: radix prune + hybrid bitonic sort ----------------
#define SM_KEYS 0
#define SM_SORT (AA * 8)                        // 67200
#define SM_HIST (SM_SORT + SORTN * 8)           // 83584
#define SM_TOPK_TOTAL (SM_HIST + 256 * 4)       // 84608

__global__ void __launch_bounds__(1024) k_topk(const float* __restrict__ pred) {
    extern __shared__ __align__(16) char sm[];
    uint64_t* skeys   = (uint64_t*)(sm + SM_KEYS);
    uint64_t* sortbuf = (uint64_t*)(sm + SM_SORT);
    uint32_t* hist    = (uint32_t*)(sm + SM_HIST);
    __shared__ uint32_t s_cnt;
    __shared__ int s_dstar, s_above;

    int b = blockIdx.x, tid = threadIdx.x;
    int lane = tid & 31;
    uint32_t lmlt = (1u << lane) - 1u;
    const uint64_t* gk = g_keys + (size_t)b * AA;

    // stage keys into smem once (coalesced)
    for (int i = tid; i < AA; i += 1024) skeys[i] = gk[i];
    __syncthreads();

    // find T with 1500 <= |{k >= T}| <= 2048 (sort finishes the selection)
    uint64_t prefix = 0, T = 0;
    int kRem = KTOP, ncand = AA, cur = 0;
    bool useAll = true;

    for (int pass = 0; pass < 8; pass++) {
        int shift = 56 - 8 * pass;
        if (tid < 256) hist[tid] = 0;
        __syncthreads();
        {   // full-mask warp-aggregated histogram (sentinel digit 256 for inactive)
            int iters = (ncand + 1023) >> 10;
            for (int it = 0; it < iters; it++) {
                int i = tid + (it << 10);
                uint32_t d = 256u;
                if (i < ncand) {
                    uint32_t item = useAll ? (uint32_t)i : g_cand[cur][b][i];
                    d = (uint32_t)(skeys[item] >> shift) & 0xFFu;
                }
                uint32_t mm = __match_any_sync(0xFFFFFFFFu, d);
                if (d < 256u && lane == (int)(__ffs(mm) - 1))
                    atomicAdd(&hist[d], (uint32_t)__popc(mm));
            }
        }
        __syncthreads();
        // single-warp digit select (descending digit order)
        if (tid < 32) {
            int base = 255 - lane * 8;
            uint32_t h[8]; uint32_t sum = 0;
#pragma unroll
            for (int k = 0; k < 8; k++) { h[k] = hist[base - k]; sum += h[k]; }
            uint32_t pre = sum;
#pragma unroll
            for (int off = 1; off < 32; off <<= 1) {
                uint32_t v = __shfl_up_sync(0xFFFFFFFFu, pre, off);
                if (lane >= off) pre += v;
            }
            uint32_t cum = pre - sum;
#pragma unroll
            for (int k = 0; k < 8; k++) {
                int d = base - k;
                if (cum < (uint32_t)kRem && cum + h[k] >= (uint32_t)kRem) {
                    s_dstar = d; s_above = (int)cum;
                }
                cum += h[k];
            }
        }
        __syncthreads();
        int ds = s_dstar;
        kRem -= s_above;
        prefix |= ((uint64_t)ds) << shift;
        int bc = (int)hist[ds];
        if ((KTOP - kRem) + bc <= SORTN || pass == 7) { T = prefix; break; }
        __syncthreads();
        if (tid == 0) s_cnt = 0;
        __syncthreads();
        {   // full-mask aggregated compaction of the tie bucket
            int iters = (ncand + 1023) >> 10;
            for (int it = 0; it < iters; it++) {
                int i = tid + (it << 10);
                uint32_t item = 0; uint32_t d = 256u;
                if (i < ncand) {
                    item = useAll ? (uint32_t)i : g_cand[cur][b][i];
                    d = (uint32_t)(skeys[item] >> shift) & 0xFFu;
                }
                bool take = (d == (uint32_t)ds);
                uint32_t bal = __ballot_sync(0xFFFFFFFFu, take);
                uint32_t base = 0;
                if (bal) {
                    uint32_t ldr = __ffs(bal) - 1;
                    if (take && lane == (int)ldr)
                        base = atomicAdd(&s_cnt, (uint32_t)__popc(bal));
                    base = __shfl_sync(0xFFFFFFFFu, base, ldr);
                    if (take)
                        g_cand[cur ^ 1][b][base + __popc(bal & lmlt)] = item;
                }
            }
        }
        __syncthreads();
        ncand = (int)s_cnt; cur ^= 1; useAll = false;
        __syncthreads();
    }

    // compact keys >= T into sortbuf (count <= 2048 guaranteed), pad with 0
    for (int i = tid; i < SORTN; i += 1024) sortbuf[i] = 0;
    if (tid == 0) s_cnt = 0;
    __syncthreads();
    {
        const int iters = (AA + 1023) >> 10;   // uniform trip count
        for (int it = 0; it < iters; it++) {
            int a = tid + (it << 10);
            uint64_t k = (a < AA) ? skeys[a] : 0ull;
            bool take = (a < AA) && (k >= T);
            uint32_t bal = __ballot_sync(0xFFFFFFFFu, take);
            uint32_t base = 0;
            if (bal) {
                uint32_t ldr = __ffs(bal) - 1;
                if (take && lane == (int)ldr)
                    base = atomicAdd(&s_cnt, (uint32_t)__popc(bal));
                base = __shfl_sync(0xFFFFFFFFu, base, ldr);
                if (take) {
                    uint32_t pos = base + __popc(bal & lmlt);
                    if (pos < SORTN) sortbuf[pos] = k;
                }
            }
        }
    }
    __syncthreads();

    // hybrid bitonic sort descending, n=2048 (shfl j<32, smem j>=32)
    {
        int i0 = tid, i1 = tid + 1024;
        uint64_t v0 = sortbuf[i0], v1 = sortbuf[i1];
#pragma unroll
        for (int kk = 2; kk <= 32; kk <<= 1) {
#pragma unroll
            for (int j = kk >> 1; j >= 1; j >>= 1) {
                v0 = bshfl(v0, i0, kk, j);
                v1 = bshfl(v1, i1, kk, j);
            }
        }
        sortbuf[i0] = v0; sortbuf[i1] = v1;
        __syncthreads();

        for (int kk = 64; kk <= SORTN; kk <<= 1) {
            for (int j = kk >> 1; j >= 32; j >>= 1) {
                for (int t = tid; t < SORTN; t += 1024) {
                    int l = t ^ j;
                    if (l > t) {
                        uint64_t x = sortbuf[t], y = sortbuf[l];
                        bool desc = ((t & kk) == 0);
                        if (desc ? (x < y) : (x > y)) { sortbuf[t] = y; sortbuf[l] = x; }
                    }
                }
                __syncthreads();
            }
            v0 = sortbuf[i0]; v1 = sortbuf[i1];
#pragma unroll
            for (int j = 16; j >= 1; j >>= 1) {
                v0 = bshfl(v0, i0, kk, j);
                v1 = bshfl(v1, i1, kk, j);
            }
            sortbuf[i0] = v0; sortbuf[i1] = v1;
            __syncthreads();
        }
    }

    // emit per-rank data + validity bitmap
    const float* pb = pred + (size_t)b * NCH * AA;
    const float SC1 = (float)(1.0 / 80.0 / 640.0);
    const float MULT = (float)(1.0 / 80.0);
#pragma unroll
    for (int rr = 0; rr < 2; rr++) {
        int r = tid + rr * 1024;
        bool inr = r < TPAD;
        bool validf = false;
        if (r < KTOP) {
            uint64_t k = sortbuf[r];
            uint32_t hi = (uint32_t)(k >> 32);
            uint32_t lo = (uint32_t)k;
            int cls = (int)(lo & 0x7Fu);
            uint32_t a = (uint32_t)(AA - 1) - (lo >> 7);
            float msc = o2f(hi);
            validf = msc > 0.25f;
            float bx0 = pb[(size_t)0 * AA + a];
            float bx1 = pb[(size_t)1 * AA + a];
            float bx2 = pb[(size_t)2 * AA + a];
            float bx3 = pb[(size_t)3 * AA + a];
            int o = b * TPAD + r;
            g_selbox[o] = make_float4(bx0, bx1, bx2, bx3);
            float off = (float)cls * MULT;
            g_nmsbox[o] = make_float4(bx0 * SC1 + off, bx1 * SC1 + off,
                                      bx2 * SC1 + off, bx3 * SC1 + off);
            g_selscore[o] = msc;
            g_selcls[o] = (float)cls;
            g_clsSel[o] = (uint8_t)cls;
        } else if (inr) {
            g_clsSel[b * TPAD + r] = 0xFFu;
        }
        uint32_t vb = __ballot_sync(0xFFFFFFFFu, validf);
        if (lane == 0 && inr) g_validbits[b * NWP + (r >> 5)] = vb;
    }
}

// ---------------- stage 3: fused per-class warp NMS + compaction + output ----------------
__global__ void __launch_bounds__(1024) k_nmsout(float* __restrict__ out) {
    __shared__ uint8_t  sCls[TPAD];
    __shared__ uint32_t sValid[NWP];
    __shared__ uint16_t slist[32][CAP];
    __shared__ uint32_t ssupp[32][NWP];
    __shared__ uint32_t sKeep[NWP];
    __shared__ uint32_t wpre[NWP];
    int b = blockIdx.x;
    int tid = threadIdx.x, warp = tid >> 5, lane = tid & 31;

    const uint32_t* gc4 = (const uint32_t*)(g_clsSel + b * TPAD);
    if (tid < TPAD / 4) ((uint32_t*)sCls)[tid] = gc4[tid];
    if (tid < NWP) { sValid[tid] = g_validbits[b * NWP + tid]; sKeep[tid] = 0; }
    float* ob = out + (size_t)b * (MAXDET * 6);
    for (int i = tid; i < MAXDET * 6; i += 1024) ob[i] = 0.0f;
    __syncthreads();

    for (int c = warp; c < NCC; c += 32) {
        // build rank-ordered candidate list for class c
        int cnt = 0;
        for (int w = 0; w < NW; w++) {
            int r = w * 32 + lane;
            bool m = (r < KTOP) && ((sValid[w] >> lane) & 1u) && (sCls[r] == (uint8_t)c);
            uint32_t bal = __ballot_sync(0xFFFFFFFFu, m);
            if (m) {
                int pos = cnt + __popc(bal & ((1u << lane) - 1u));
                if (pos < CAP) slist[warp][pos] = (uint16_t)r;
            }
            cnt += __popc(bal);
        }
        int n = cnt;
        if (n == 0) continue;

        if (n <= 32) {
            // register-resident greedy NMS
            float4 mb = make_float4(0.f, 0.f, 0.f, 0.f);
            int myr = -1;
            if (lane < n) { myr = slist[warp][lane]; mb = g_nmsbox[b * TPAD + myr]; }
            float areaM = (mb.z - mb.x) * (mb.w - mb.y);
            uint32_t supp = 0;
            for (int i = 0; i < n; i++) {
                if ((supp >> i) & 1u) continue;
                float ax = __shfl_sync(0xFFFFFFFFu, mb.x, i);
                float ay = __shfl_sync(0xFFFFFFFFu, mb.y, i);
                float az = __shfl_sync(0xFFFFFFFFu, mb.z, i);
                float aw = __shfl_sync(0xFFFFFFFFu, mb.w, i);
                float areaA = (az - ax) * (aw - ay);
                float lx = fmaxf(ax, mb.x), ly = fmaxf(ay, mb.y);
                float rx = fminf(az, mb.z), ry = fminf(aw, mb.w);
                float inter = fmaxf(rx - lx, 0.f) * fmaxf(ry - ly, 0.f);
                float iou = inter / (areaA + areaM - inter + 1e-7f);
                bool sbit = (lane > i) && (lane < n) && (iou > 0.45f);
                supp |= __ballot_sync(0xFFFFFFFFu, sbit);
            }
            if (lane < n && !((supp >> lane) & 1u))
                atomicOr(&sKeep[myr >> 5], 1u << (myr & 31));
        } else if (n <= CAP) {
            int words = (n + 31) >> 5;
            for (int w = lane; w < words; w += 32) ssupp[warp][w] = 0;
            __syncwarp();
            for (int i = 0; i < n; i++) {
                if ((ssupp[warp][i >> 5] >> (i & 31)) & 1u) continue;
                float4 a = g_nmsbox[b * TPAD + slist[warp][i]];
                float areaA = (a.z - a.x) * (a.w - a.y);
                for (int w = i >> 5; w < words; w++) {
                    int j = w * 32 + lane;
                    bool sbit = false;
                    if (j > i && j < n) {
                        float4 bb = g_nmsbox[b * TPAD + slist[warp][j]];
                        float areaB = (bb.z - bb.x) * (bb.w - bb.y);
                        float lx = fmaxf(a.x, bb.x), ly = fmaxf(a.y, bb.y);
                        float rx = fminf(a.z, bb.z), ry = fminf(a.w, bb.w);
                        float inter = fmaxf(rx - lx, 0.f) * fmaxf(ry - ly, 0.f);
                        float iou = inter / (areaA + areaB - inter + 1e-7f);
                        sbit = iou > 0.45f;
                    }
                    uint32_t bal = __ballot_sync(0xFFFFFFFFu, sbit);
                    if (lane == 0 && bal) ssupp[warp][w] |= bal;
                    __syncwarp();
                }
            }
            for (int j = lane; j < n; j += 32)
                if (!((ssupp[warp][j >> 5] >> (j & 31)) & 1u)) {
                    int r = slist[warp][j];
                    atomicOr(&sKeep[r >> 5], 1u << (r & 31));
                }
        } else {
            // overflow fallback: rank-bitmap greedy over all 1500 (always correct)
            uint32_t* sp = ssupp[warp];
            for (int w = lane; w < NWP; w += 32) sp[w] = 0;
            __syncwarp();
            for (int i = 0; i < KTOP; i++) {
                bool mem = (sCls[i] == (uint8_t)c) && ((sValid[i >> 5] >> (i & 31)) & 1u)
                           && !((sp[i >> 5] >> (i & 31)) & 1u);
                if (!mem) continue;
                float4 a = g_nmsbox[b * TPAD + i];
                float areaA = (a.z - a.x) * (a.w - a.y);
                for (int w = i >> 5; w < NW; w++) {
                    int j = w * 32 + lane;
                    bool sbit = false;
                    if (j > i && j < KTOP && ((sValid[w] >> lane) & 1u)
                        && sCls[j] == (uint8_t)c) {
                        float4 bb = g_nmsbox[b * TPAD + j];
                        float areaB = (bb.z - bb.x) * (bb.w - bb.y);
                        float lx = fmaxf(a.x, bb.x), ly = fmaxf(a.y, bb.y);
                        float rx = fminf(a.z, bb.z), ry = fminf(a.w, bb.w);
                        float inter = fmaxf(rx - lx, 0.f) * fmaxf(ry - ly, 0.f);
                        float iou = inter / (areaA + areaB - inter + 1e-7f);
                        sbit = iou > 0.45f;
                    }
                    uint32_t bal = __ballot_sync(0xFFFFFFFFu, sbit);
                    if (lane == 0 && bal) sp[w] |= bal;
                    __syncwarp();
                }
            }
            for (int r = lane; r < KTOP; r += 32) {
                bool mem = (sCls[r] == (uint8_t)c) && ((sValid[r >> 5] >> (r & 31)) & 1u)
                           && !((sp[r >> 5] >> (r & 31)) & 1u);
                if (mem) atomicOr(&sKeep[r >> 5], 1u << (r & 31));
            }
        }
    }
    __syncthreads();

    // warp 0: exclusive prefix over 48 keep words
    if (warp == 0) {
        uint32_t c0 = (lane < NWP) ? __popc(sKeep[lane]) : 0;
        uint32_t inc = c0;
#pragma unroll
        for (int off = 1; off < 32; off <<= 1) {
            uint32_t v = __shfl_up_sync(0xFFFFFFFFu, inc, off);
            if (lane >= off) inc += v;
        }
        wpre[lane] = inc - c0;
        uint32_t tot0 = __shfl_sync(0xFFFFFFFFu, inc, 31);
        uint32_t c1 = (lane + 32 < NWP) ? __popc(sKeep[lane + 32]) : 0;
        uint32_t inc1 = c1;
#pragma unroll
        for (int off = 1; off < 32; off <<= 1) {
            uint32_t v = __shfl_up_sync(0xFFFFFFFFu, inc1, off);
            if (lane >= off) inc1 += v;
        }
        if (lane + 32 < NWP) wpre[lane + 32] = tot0 + inc1 - c1;
    }
    __syncthreads();

    // scatter kept dets in rank order
    for (int r = tid; r < KTOP; r += 1024) {
        int w = r >> 5;
        uint32_t word = sKeep[w];
        uint32_t bit = 1u << (r & 31);
        if (word & bit) {
            uint32_t rank = wpre[w] + __popc(word & (bit - 1u));
            if (rank < MAXDET) {
                float4 bx = g_selbox[b * TPAD + r];
                float* o = ob + rank * 6;
                o[0] = bx.x; o[1] = bx.y; o[2] = bx.z; o[3] = bx.w;
                o[4] = g_selscore[b * TPAD + r];
                o[5] = g_selcls[b * TPAD + r];
            }
        }
    }
}

// ---------------- launch ----------------
extern "C" void kernel_launch(void* const* d_in, const int* in_sizes, int n_in,
                              void* d_out, int out_size) {
    const float* pred = (const float*)d_in[0];
    float* out = (float*)d_out;
    cudaFuncSetAttribute(k_topk, cudaFuncAttributeMaxDynamicSharedMemorySize,
                         SM_TOPK_TOTAL);
    k_score<<<dim3((AA / 4 + 255) / 256, BB), 256>>>(pred);
    k_topk<<<BB, 1024, SM_TOPK_TOTAL>>>(pred);
    k_nmsout<<<BB, 1024>>>(out);
}

// round 6
// speedup vs baseline: 1.1789x; 1.1789x over previous
#include <cuda_runtime.h>
#include <cstdint>

#define BB 32
#define AA 8400
#define NCH 84
#define NCC 80
#define KTOP 1500
#define TPAD 1536
#define SORTN 2048
#define MAXDET 300
#define NW 47
#define NWP 48

// ---------------- device scratch (static, allocation-free) ----------------
__device__ uint64_t g_keys[BB * AA];
__device__ uint32_t g_cand[2][BB][AA];
__device__ float4   g_selbox[BB * TPAD];
__device__ float4   g_nmsbox[BB * TPAD];
__device__ float    g_selscore[BB * TPAD];
__device__ float    g_selcls[BB * TPAD];
__device__ uint8_t  g_clsSel[BB * TPAD];
__device__ uint32_t g_validbits[BB * NWP];
__device__ uint8_t  g_keepB[BB * TPAD];

__device__ __forceinline__ uint32_t f2o(float f) {
    uint32_t u = __float_as_uint(f);
    return (u & 0x80000000u) ? ~u : (u | 0x80000000u);
}
__device__ __forceinline__ float o2f(uint32_t u) {
    return (u & 0x80000000u) ? __uint_as_float(u & 0x7FFFFFFFu)
                             : __uint_as_float(~u);
}

__device__ __forceinline__ uint64_t bshfl(uint64_t v, int i, int kk, int j) {
    uint64_t p = __shfl_xor_sync(0xFFFFFFFFu, v, j);
    bool up = (i & j) == 0;
    bool desc = (i & kk) == 0;
    bool takemax = (up == desc);
    return ((v > p) == takemax) ? v : p;
}

// ---------------- stage 1: score max/argmax (4-way class split) ----------------
// Thread group of 4 (h = lane&3) splits the 80 classes into 4 x 20; two
// shfl_xor reduction steps combine (score, cls) with smaller-class tie-break
// (== argmax first-occurrence). key = f2o(msc)<<32 | (AA-1-a)<<7 | cls.
__global__ void __launch_bounds__(256) k_score(const float* __restrict__ pred) {
    const int Q = AA / 4;                       // 2100 anchor-groups
    int t = blockIdx.x * blockDim.x + threadIdx.x;
    int b = blockIdx.y;
    int q = t >> 2;
    int h = t & 3;
    bool active = q < Q;
    if (q >= Q) q = Q - 1;                      // clamp: keep warp converged

    const float4* p4 = (const float4*)pred;
    size_t base = ((size_t)b * NCH + 4) * Q + q;
    int c0 = h * 20;

    float4 best = p4[base + (size_t)c0 * Q];
    int cx = c0, cy = c0, cz = c0, cw = c0;
#pragma unroll
    for (int k = 1; k < 20; k++) {
        int c = c0 + k;
        float4 v = p4[base + (size_t)c * Q];
        if (v.x > best.x) { best.x = v.x; cx = c; }
        if (v.y > best.y) { best.y = v.y; cy = c; }
        if (v.z > best.z) { best.z = v.z; cz = c; }
        if (v.w > best.w) { best.w = v.w; cw = c; }
    }

    float sc[4] = {best.x, best.y, best.z, best.w};
    int   cl[4] = {cx, cy, cz, cw};
#pragma unroll
    for (int step = 1; step <= 2; step <<= 1) {
#pragma unroll
        for (int u = 0; u < 4; u++) {
            float so = __shfl_xor_sync(0xFFFFFFFFu, sc[u], step);
            int   co = __shfl_xor_sync(0xFFFFFFFFu, cl[u], step);
            if (so > sc[u] || (so == sc[u] && co < cl[u])) { sc[u] = so; cl[u] = co; }
        }
    }

    if (h == 0 && active) {
        int a0 = q * 4;
#pragma unroll
        for (int u = 0; u < 4; u++) {
            int a = a0 + u;
            float msc = (sc[u] > 0.25f) ? sc[u] : -1.0f;
            uint32_t lo = ((uint32_t)(AA - 1 - a) << 7) | (uint32_t)cl[u];
            g_keys[b * AA + a] = ((uint64_t)f2o(msc) << 32) | lo;
        }
    }
}

// ---------------- stage 2: radix prune + hybrid bitonic sort ----------------
#define SM_KEYS 0
#define SM_SORT (AA * 8)                        // 67200
#define SM_HIST (SM_SORT + SORTN * 8)           // 83584
#define SM_TOPK_TOTAL (SM_HIST + 256 * 4)       // 84608

__global__ void __launch_bounds__(1024) k_topk(const float* __restrict__ pred) {
    extern __shared__ __align__(16) char sm[];
    uint64_t* skeys   = (uint64_t*)(sm + SM_KEYS);
    uint64_t* sortbuf = (uint64_t*)(sm + SM_SORT);
    uint32_t* hist    = (uint32_t*)(sm + SM_HIST);
    __shared__ uint32_t s_cnt;
    __shared__ int s_dstar, s_above;

    int b = blockIdx.x, tid = threadIdx.x;
    int lane = tid & 31;
    uint32_t lmlt = (1u << lane) - 1u;
    const uint64_t* gk = g_keys + (size_t)b * AA;

    for (int i = tid; i < AA; i += 1024) skeys[i] = gk[i];
    __syncthreads();

    uint64_t prefix = 0, T = 0;
    int kRem = KTOP, ncand = AA, cur = 0;
    bool useAll = true;

    for (int pass = 0; pass < 8; pass++) {
        int shift = 56 - 8 * pass;
        if (tid < 256) hist[tid] = 0;
        __syncthreads();
        {
            int iters = (ncand + 1023) >> 10;
            for (int it = 0; it < iters; it++) {
                int i = tid + (it << 10);
                uint32_t d = 256u;
                if (i < ncand) {
                    uint32_t item = useAll ? (uint32_t)i : g_cand[cur][b][i];
                    d = (uint32_t)(skeys[item] >> shift) & 0xFFu;
                }
                uint32_t mm = __match_any_sync(0xFFFFFFFFu, d);
                if (d < 256u && lane == (int)(__ffs(mm) - 1))
                    atomicAdd(&hist[d], (uint32_t)__popc(mm));
            }
        }
        __syncthreads();
        if (tid < 32) {
            int base = 255 - lane * 8;
            uint32_t h[8]; uint32_t sum = 0;
#pragma unroll
            for (int k = 0; k < 8; k++) { h[k] = hist[base - k]; sum += h[k]; }
            uint32_t pre = sum;
#pragma unroll
            for (int off = 1; off < 32; off <<= 1) {
                uint32_t v = __shfl_up_sync(0xFFFFFFFFu, pre, off);
                if (lane >= off) pre += v;
            }
            uint32_t cum = pre - sum;
#pragma unroll
            for (int k = 0; k < 8; k++) {
                int d = base - k;
                if (cum < (uint32_t)kRem && cum + h[k] >= (uint32_t)kRem) {
                    s_dstar = d; s_above = (int)cum;
                }
                cum += h[k];
            }
        }
        __syncthreads();
        int ds = s_dstar;
        kRem -= s_above;
        prefix |= ((uint64_t)ds) << shift;
        int bc = (int)hist[ds];
        if ((KTOP - kRem) + bc <= SORTN || pass == 7) { T = prefix; break; }
        __syncthreads();
        if (tid == 0) s_cnt = 0;
        __syncthreads();
        {
            int iters = (ncand + 1023) >> 10;
            for (int it = 0; it < iters; it++) {
                int i = tid + (it << 10);
                uint32_t item = 0; uint32_t d = 256u;
                if (i < ncand) {
                    item = useAll ? (uint32_t)i : g_cand[cur][b][i];
                    d = (uint32_t)(skeys[item] >> shift) & 0xFFu;
                }
                bool take = (d == (uint32_t)ds);
                uint32_t bal = __ballot_sync(0xFFFFFFFFu, take);
                uint32_t base = 0;
                if (bal) {
                    uint32_t ldr = __ffs(bal) - 1;
                    if (take && lane == (int)ldr)
                        base = atomicAdd(&s_cnt, (uint32_t)__popc(bal));
                    base = __shfl_sync(0xFFFFFFFFu, base, ldr);
                    if (take)
                        g_cand[cur ^ 1][b][base + __popc(bal & lmlt)] = item;
                }
            }
        }
        __syncthreads();
        ncand = (int)s_cnt; cur ^= 1; useAll = false;
        __syncthreads();
    }

    for (int i = tid; i < SORTN; i += 1024) sortbuf[i] = 0;
    if (tid == 0) s_cnt = 0;
    for (int i = tid; i < TPAD; i += 1024) g_keepB[b * TPAD + i] = 0;
    __syncthreads();
    {
        const int iters = (AA + 1023) >> 10;
        for (int it = 0; it < iters; it++) {
            int a = tid + (it << 10);
            uint64_t k = (a < AA) ? skeys[a] : 0ull;
            bool take = (a < AA) && (k >= T);
            uint32_t bal = __ballot_sync(0xFFFFFFFFu, take);
            uint32_t base = 0;
            if (bal) {
                uint32_t ldr = __ffs(bal) - 1;
                if (take && lane == (int)ldr)
                    base = atomicAdd(&s_cnt, (uint32_t)__popc(bal));
                base = __shfl_sync(0xFFFFFFFFu, base, ldr);
                if (take) {
                    uint32_t pos = base + __popc(bal & lmlt);
                    if (pos < SORTN) sortbuf[pos] = k;
                }
            }
        }
    }
    __syncthreads();

    {
        int i0 = tid, i1 = tid + 1024;
        uint64_t v0 = sortbuf[i0], v1 = sortbuf[i1];
#pragma unroll
        for (int kk = 2; kk <= 32; kk <<= 1) {
#pragma unroll
            for (int j = kk >> 1; j >= 1; j >>= 1) {
                v0 = bshfl(v0, i0, kk, j);
                v1 = bshfl(v1, i1, kk, j);
            }
        }
        sortbuf[i0] = v0; sortbuf[i1] = v1;
        __syncthreads();

        for (int kk = 64; kk <= SORTN; kk <<= 1) {
            for (int j = kk >> 1; j >= 32; j >>= 1) {
                for (int t = tid; t < SORTN; t += 1024) {
                    int l = t ^ j;
                    if (l > t) {
                        uint64_t x = sortbuf[t], y = sortbuf[l];
                        bool desc = ((t & kk) == 0);
                        if (desc ? (x < y) : (x > y)) { sortbuf[t] = y; sortbuf[l] = x; }
                    }
                }
                __syncthreads();
            }
            v0 = sortbuf[i0]; v1 = sortbuf[i1];
#pragma unroll
            for (int j = 16; j >= 1; j >>= 1) {
                v0 = bshfl(v0, i0, kk, j);
                v1 = bshfl(v1, i1, kk, j);
            }
            sortbuf[i0] = v0; sortbuf[i1] = v1;
            __syncthreads();
        }
    }

    const float* pb = pred + (size_t)b * NCH * AA;
    const float SC1 = (float)(1.0 / 80.0 / 640.0);
    const float MULT = (float)(1.0 / 80.0);
#pragma unroll
    for (int rr = 0; rr < 2; rr++) {
        int r = tid + rr * 1024;
        bool inr = r < TPAD;
        bool validf = false;
        if (r < KTOP) {
            uint64_t k = sortbuf[r];
            uint32_t hi = (uint32_t)(k >> 32);
            uint32_t lo = (uint32_t)k;
            int cls = (int)(lo & 0x7Fu);
            uint32_t a = (uint32_t)(AA - 1) - (lo >> 7);
            float msc = o2f(hi);
            validf = msc > 0.25f;
            float bx0 = pb[(size_t)0 * AA + a];
            float bx1 = pb[(size_t)1 * AA + a];
            float bx2 = pb[(size_t)2 * AA + a];
            float bx3 = pb[(size_t)3 * AA + a];
            int o = b * TPAD + r;
            g_selbox[o] = make_float4(bx0, bx1, bx2, bx3);
            float off = (float)cls * MULT;
            g_nmsbox[o] = make_float4(bx0 * SC1 + off, bx1 * SC1 + off,
                                      bx2 * SC1 + off, bx3 * SC1 + off);
            g_selscore[o] = msc;
            g_selcls[o] = (float)cls;
            g_clsSel[o] = (uint8_t)cls;
        } else if (inr) {
            g_clsSel[b * TPAD + r] = 0xFFu;
        }
        uint32_t vb = __ballot_sync(0xFFFFFFFFu, validf);
        if (lane == 0 && inr) g_validbits[b * NWP + (r >> 5)] = vb;
    }
}

// ---------------- stage 3: per-(image,class) warp NMS (one class per warp) ----------------
__global__ void k_nms() {
    __shared__ uint8_t  sCls[TPAD];
    __shared__ uint32_t sValid[NWP];
    __shared__ uint16_t slist[8][TPAD];
    __shared__ uint32_t ssupp[8][NWP];
    int b = blockIdx.y;
    int tid = threadIdx.x, warp = tid >> 5, lane = tid & 31;
    int c = blockIdx.x * 8 + warp;              // 10 x 8 = 80 classes exactly

    const uint32_t* gc4 = (const uint32_t*)(g_clsSel + b * TPAD);
    uint32_t* sc4 = (uint32_t*)sCls;
    for (int i = tid; i < TPAD / 4; i += 256) sc4[i] = gc4[i];
    if (tid < NWP) sValid[tid] = g_validbits[b * NWP + tid];
    __syncthreads();

    int cnt = 0;
    for (int w = 0; w < NW; w++) {
        int r = w * 32 + lane;
        bool m = (r < KTOP) && ((sValid[w] >> lane) & 1u) && (sCls[r] == (uint8_t)c);
        uint32_t bal = __ballot_sync(0xFFFFFFFFu, m);
        if (m) slist[warp][cnt + __popc(bal & ((1u << lane) - 1u))] = (uint16_t)r;
        cnt += __popc(bal);
    }
    int n = cnt;
    if (n == 0) return;

    if (n <= 32) {
        float4 mb = make_float4(0.f, 0.f, 0.f, 0.f);
        int myr = -1;
        if (lane < n) { myr = slist[warp][lane]; mb = g_nmsbox[b * TPAD + myr]; }
        float areaM = (mb.z - mb.x) * (mb.w - mb.y);
        uint32_t supp = 0;
        for (int i = 0; i < n; i++) {
            if ((supp >> i) & 1u) continue;
            float ax = __shfl_sync(0xFFFFFFFFu, mb.x, i);
            float ay = __shfl_sync(0xFFFFFFFFu, mb.y, i);
            float az = __shfl_sync(0xFFFFFFFFu, mb.z, i);
            float aw = __shfl_sync(0xFFFFFFFFu, mb.w, i);
            float areaA = (az - ax) * (aw - ay);
            float lx = fmaxf(ax, mb.x), ly = fmaxf(ay, mb.y);
            float rx = fminf(az, mb.z), ry = fminf(aw, mb.w);
            float inter = fmaxf(rx - lx, 0.f) * fmaxf(ry - ly, 0.f);
            float iou = inter / (areaA + areaM - inter + 1e-7f);
            bool sbit = (lane > i) && (lane < n) && (iou > 0.45f);
            supp |= __ballot_sync(0xFFFFFFFFu, sbit);
        }
        if (lane < n && !((supp >> lane) & 1u)) g_keepB[b * TPAD + myr] = 1;
    } else {
        int words = (n + 31) >> 5;
        for (int w = lane; w < words; w += 32) ssupp[warp][w] = 0;
        __syncwarp();
        for (int i = 0; i < n; i++) {
            if ((ssupp[warp][i >> 5] >> (i & 31)) & 1u) continue;
            float4 a = g_nmsbox[b * TPAD + slist[warp][i]];
            float areaA = (a.z - a.x) * (a.w - a.y);
            for (int w = i >> 5; w < words; w++) {
                int j = w * 32 + lane;
                bool sbit = false;
                if (j > i && j < n) {
                    float4 bb = g_nmsbox[b * TPAD + slist[warp][j]];
                    float areaB = (bb.z - bb.x) * (bb.w - bb.y);
                    float lx = fmaxf(a.x, bb.x), ly = fmaxf(a.y, bb.y);
                    float rx = fminf(a.z, bb.z), ry = fminf(a.w, bb.w);
                    float inter = fmaxf(rx - lx, 0.f) * fmaxf(ry - ly, 0.f);
                    float iou = inter / (areaA + areaB - inter + 1e-7f);
                    sbit = iou > 0.45f;
                }
                uint32_t bal = __ballot_sync(0xFFFFFFFFu, sbit);
                if (lane == 0 && bal) ssupp[warp][w] |= bal;
                __syncwarp();
            }
        }
        for (int j = lane; j < n; j += 32)
            if (!((ssupp[warp][j >> 5] >> (j & 31)) & 1u))
                g_keepB[b * TPAD + slist[warp][j]] = 1;
    }
}

// ---------------- stage 4: parallel rank compaction + output ----------------
__global__ void __launch_bounds__(256) k_out(float* __restrict__ out) {
    __shared__ uint32_t keepw[NWP], wpre[NWP];
    int b = blockIdx.x, tid = threadIdx.x;
    int warp = tid >> 5, lane = tid & 31;

    float* ob = out + (size_t)b * (MAXDET * 6);
    for (int i = tid; i < MAXDET * 6; i += 256) ob[i] = 0.0f;

    uint8_t kb[6];
#pragma unroll
    for (int s = 0; s < 6; s++) {
        int w = warp * 6 + s;
        kb[s] = g_keepB[b * TPAD + w * 32 + lane];
    }
#pragma unroll
    for (int s = 0; s < 6; s++) {
        uint32_t word = __ballot_sync(0xFFFFFFFFu, kb[s] != 0);
        if (lane == 0) keepw[warp * 6 + s] = word;
    }
    __syncthreads();
    if (tid == 0) {
        uint32_t s = 0;
        for (int w = 0; w < NWP; w++) { wpre[w] = s; s += __popc(keepw[w]); }
    }
    __syncthreads();
    for (int r = tid; r < KTOP; r += 256) {
        int w = r >> 5;
        uint32_t word = keepw[w];
        uint32_t bit = 1u << (r & 31);
        if (word & bit) {
            uint32_t rank = wpre[w] + __popc(word & (bit - 1u));
            if (rank < MAXDET) {
                float4 bx = g_selbox[b * TPAD + r];
                float* o = ob + rank * 6;
                o[0] = bx.x; o[1] = bx.y; o[2] = bx.z; o[3] = bx.w;
                o[4] = g_selscore[b * TPAD + r];
                o[5] = g_selcls[b * TPAD + r];
            }
        }
    }
}

// ---------------- launch ----------------
extern "C" void kernel_launch(void* const* d_in, const int* in_sizes, int n_in,
                              void* d_out, int out_size) {
    const float* pred = (const float*)d_in[0];
    float* out = (float*)d_out;
    cudaFuncSetAttribute(k_topk, cudaFuncAttributeMaxDynamicSharedMemorySize,
                         SM_TOPK_TOTAL);
    k_score<<<dim3((AA + 255) / 256, BB), 256>>>(pred);
    k_topk<<<BB, 1024, SM_TOPK_TOTAL>>>(pred);
    k_nms<<<dim3(10, BB), 256>>>();
    k_out<<<BB, 256>>>(out);
}

// round 7
// speedup vs baseline: 1.2319x; 1.0449x over previous
#include <cuda_runtime.h>
#include <cstdint>

#define BB 32
#define AA 8400
#define NCH 84
#define NCC 80
#define KTOP 1500
#define TPAD 1536
#define SORTN 2048
#define MAXDET 300
#define NW 47
#define NWP 48

// ---------------- device scratch (static, allocation-free) ----------------
__device__ uint64_t g_keys[BB * AA];
__device__ uint32_t g_cand[2][BB][AA];
__device__ float4   g_selbox[BB * TPAD];
__device__ float4   g_nmsbox[BB * TPAD];
__device__ float    g_selscore[BB * TPAD];
__device__ float    g_selcls[BB * TPAD];
__device__ uint8_t  g_clsSel[BB * TPAD];
__device__ uint32_t g_validbits[BB * NWP];
__device__ uint8_t  g_keepB[BB * TPAD];
__device__ uint32_t g_done[BB];

__device__ __forceinline__ uint32_t f2o(float f) {
    uint32_t u = __float_as_uint(f);
    return (u & 0x80000000u) ? ~u : (u | 0x80000000u);
}
__device__ __forceinline__ float o2f(uint32_t u) {
    return (u & 0x80000000u) ? __uint_as_float(u & 0x7FFFFFFFu)
                             : __uint_as_float(~u);
}

// ---------------- stage 1: score max/argmax (4-way class split) ----------------
// key = f2o(masked_score)<<32 | (AA-1-a)<<7 | cls  (index above class bits
// preserves exact lax.top_k tie order: lower anchor index first)
__global__ void __launch_bounds__(256) k_score(const float* __restrict__ pred) {
    const int Q = AA / 4;                       // 2100 anchor-groups
    int t = blockIdx.x * blockDim.x + threadIdx.x;
    int b = blockIdx.y;
    int q = t >> 2;
    int h = t & 3;
    bool active = q < Q;
    if (q >= Q) q = Q - 1;                      // clamp: keep warp converged

    const float4* p4 = (const float4*)pred;
    size_t base = ((size_t)b * NCH + 4) * Q + q;
    int c0 = h * 20;

    float4 best = p4[base + (size_t)c0 * Q];
    int cx = c0, cy = c0, cz = c0, cw = c0;
#pragma unroll
    for (int k = 1; k < 20; k++) {
        int c = c0 + k;
        float4 v = p4[base + (size_t)c * Q];
        if (v.x > best.x) { best.x = v.x; cx = c; }
        if (v.y > best.y) { best.y = v.y; cy = c; }
        if (v.z > best.z) { best.z = v.z; cz = c; }
        if (v.w > best.w) { best.w = v.w; cw = c; }
    }

    float sc[4] = {best.x, best.y, best.z, best.w};
    int   cl[4] = {cx, cy, cz, cw};
#pragma unroll
    for (int step = 1; step <= 2; step <<= 1) {
#pragma unroll
        for (int u = 0; u < 4; u++) {
            float so = __shfl_xor_sync(0xFFFFFFFFu, sc[u], step);
            int   co = __shfl_xor_sync(0xFFFFFFFFu, cl[u], step);
            if (so > sc[u] || (so == sc[u] && co < cl[u])) { sc[u] = so; cl[u] = co; }
        }
    }

    if (h == 0 && active) {
        int a0 = q * 4;
#pragma unroll
        for (int u = 0; u < 4; u++) {
            int a = a0 + u;
            float msc = (sc[u] > 0.25f) ? sc[u] : -1.0f;
            uint32_t lo = ((uint32_t)(AA - 1 - a) << 7) | (uint32_t)cl[u];
            g_keys[b * AA + a] = ((uint64_t)f2o(msc) << 32) | lo;
        }
    }
}

// ---------------- stage 2: radix prune (early exit) + bitonic sort (R3 style) ----------------
__global__ void __launch_bounds__(1024) k_topk(const float* __restrict__ pred) {
    __shared__ uint32_t hist[256];
    __shared__ uint64_t sortbuf[SORTN];
    __shared__ uint32_t s_cnt;
    __shared__ int s_dstar, s_above;

    int b = blockIdx.x, tid = threadIdx.x;
    int lane = tid & 31;
    const uint64_t* keys = g_keys + (size_t)b * AA;

    // find T with 1500 <= |{k >= T}| <= 2048 (sort finishes the selection)
    uint64_t prefix = 0, T = 0;
    int kRem = KTOP, ncand = AA, cur = 0;
    bool useAll = true;

    for (int pass = 0; pass < 8; pass++) {
        int shift = 56 - 8 * pass;
        if (tid < 256) hist[tid] = 0;
        __syncthreads();
        for (int i = tid; i < ncand; i += 1024) {
            uint32_t item = useAll ? (uint32_t)i : g_cand[cur][b][i];
            uint32_t d = (uint32_t)(keys[item] >> shift) & 0xFFu;
            atomicAdd(&hist[d], 1u);
        }
        __syncthreads();
        // single-warp digit select (descending digit order)
        if (tid < 32) {
            int base = 255 - lane * 8;
            uint32_t h[8]; uint32_t sum = 0;
#pragma unroll
            for (int k = 0; k < 8; k++) { h[k] = hist[base - k]; sum += h[k]; }
            uint32_t pre = sum;
#pragma unroll
            for (int off = 1; off < 32; off <<= 1) {
                uint32_t v = __shfl_up_sync(0xFFFFFFFFu, pre, off);
                if (lane >= off) pre += v;
            }
            uint32_t cum = pre - sum;
#pragma unroll
            for (int k = 0; k < 8; k++) {
                int d = base - k;
                if (cum < (uint32_t)kRem && cum + h[k] >= (uint32_t)kRem) {
                    s_dstar = d; s_above = (int)cum;
                }
                cum += h[k];
            }
        }
        __syncthreads();
        int ds = s_dstar;
        kRem -= s_above;
        prefix |= ((uint64_t)ds) << shift;
        int bc = (int)hist[ds];
        if ((KTOP - kRem) + bc <= SORTN || pass == 7) { T = prefix; break; }
        __syncthreads();
        if (tid == 0) s_cnt = 0;
        __syncthreads();
        for (int i = tid; i < ncand; i += 1024) {
            uint32_t item = useAll ? (uint32_t)i : g_cand[cur][b][i];
            uint32_t d = (uint32_t)(keys[item] >> shift) & 0xFFu;
            if (d == (uint32_t)ds) {
                uint32_t p = atomicAdd(&s_cnt, 1u);
                g_cand[cur ^ 1][b][p] = item;
            }
        }
        __syncthreads();
        ncand = (int)s_cnt; cur ^= 1; useAll = false;
        __syncthreads();
    }

    // compact keys >= T into smem (count <= 2048 guaranteed), pad with 0
    for (int i = tid; i < SORTN; i += 1024) sortbuf[i] = 0;
    if (tid == 0) { s_cnt = 0; g_done[b] = 0; }
    for (int i = tid; i < TPAD; i += 1024) g_keepB[b * TPAD + i] = 0;
    __syncthreads();
    for (int a = tid; a < AA; a += 1024) {
        uint64_t k = keys[a];
        if (k >= T) {
            uint32_t p = atomicAdd(&s_cnt, 1u);
            if (p < SORTN) sortbuf[p] = k;
        }
    }
    __syncthreads();

    // bitonic sort descending, n=2048
    for (int kk = 2; kk <= SORTN; kk <<= 1) {
        for (int j = kk >> 1; j > 0; j >>= 1) {
            for (int t = tid; t < SORTN; t += 1024) {
                int l = t ^ j;
                if (l > t) {
                    uint64_t x = sortbuf[t], y = sortbuf[l];
                    bool desc = ((t & kk) == 0);
                    if (desc ? (x < y) : (x > y)) { sortbuf[t] = y; sortbuf[l] = x; }
                }
            }
            __syncthreads();
        }
    }

    // emit per-rank data + validity bitmap
    const float* pb = pred + (size_t)b * NCH * AA;
    const float SC1 = (float)(1.0 / 80.0 / 640.0);
    const float MULT = (float)(1.0 / 80.0);
#pragma unroll
    for (int rr = 0; rr < 2; rr++) {
        int r = tid + rr * 1024;
        bool inr = r < TPAD;
        bool validf = false;
        if (r < KTOP) {
            uint64_t k = sortbuf[r];
            uint32_t hi = (uint32_t)(k >> 32);
            uint32_t lo = (uint32_t)k;
            int cls = (int)(lo & 0x7Fu);
            uint32_t a = (uint32_t)(AA - 1) - (lo >> 7);
            float msc = o2f(hi);
            validf = msc > 0.25f;
            float bx0 = pb[(size_t)0 * AA + a];
            float bx1 = pb[(size_t)1 * AA + a];
            float bx2 = pb[(size_t)2 * AA + a];
            float bx3 = pb[(size_t)3 * AA + a];
            int o = b * TPAD + r;
            g_selbox[o] = make_float4(bx0, bx1, bx2, bx3);
            float off = (float)cls * MULT;
            g_nmsbox[o] = make_float4(bx0 * SC1 + off, bx1 * SC1 + off,
                                      bx2 * SC1 + off, bx3 * SC1 + off);
            g_selscore[o] = msc;
            g_selcls[o] = (float)cls;
            g_clsSel[o] = (uint8_t)cls;
        } else if (inr) {
            g_clsSel[b * TPAD + r] = 0xFFu;
        }
        uint32_t vb = __ballot_sync(0xFFFFFFFFu, validf);
        if (lane == 0 && inr) g_validbits[b * NWP + (r >> 5)] = vb;
    }
}

// ---------------- stage 3: per-class warp NMS + last-block fused output ----------------
__global__ void k_nms(float* __restrict__ out) {
    __shared__ uint8_t  sCls[TPAD];
    __shared__ uint32_t sValid[NWP];
    __shared__ uint16_t slist[8][TPAD];
    __shared__ uint32_t ssupp[8][NWP];
    __shared__ uint32_t keepw[NWP], wpre[NWP];
    __shared__ int s_last;
    int b = blockIdx.y;
    int tid = threadIdx.x, warp = tid >> 5, lane = tid & 31;
    int c = blockIdx.x * 8 + warp;              // 10 x 8 = 80 classes exactly

    const uint32_t* gc4 = (const uint32_t*)(g_clsSel + b * TPAD);
    uint32_t* sc4 = (uint32_t*)sCls;
    for (int i = tid; i < TPAD / 4; i += 256) sc4[i] = gc4[i];
    if (tid < NWP) sValid[tid] = g_validbits[b * NWP + tid];
    __syncthreads();

    // build rank-ordered candidate list for class c
    int cnt = 0;
    for (int w = 0; w < NW; w++) {
        int r = w * 32 + lane;
        bool m = (r < KTOP) && ((sValid[w] >> lane) & 1u) && (sCls[r] == (uint8_t)c);
        uint32_t bal = __ballot_sync(0xFFFFFFFFu, m);
        if (m) slist[warp][cnt + __popc(bal & ((1u << lane) - 1u))] = (uint16_t)r;
        cnt += __popc(bal);
    }
    int n = cnt;

    if (n > 0 && n <= 32) {
        float4 mb = make_float4(0.f, 0.f, 0.f, 0.f);
        int myr = -1;
        if (lane < n) { myr = slist[warp][lane]; mb = g_nmsbox[b * TPAD + myr]; }
        float areaM = (mb.z - mb.x) * (mb.w - mb.y);
        uint32_t supp = 0;
        for (int i = 0; i < n; i++) {
            if ((supp >> i) & 1u) continue;
            float ax = __shfl_sync(0xFFFFFFFFu, mb.x, i);
            float ay = __shfl_sync(0xFFFFFFFFu, mb.y, i);
            float az = __shfl_sync(0xFFFFFFFFu, mb.z, i);
            float aw = __shfl_sync(0xFFFFFFFFu, mb.w, i);
            float areaA = (az - ax) * (aw - ay);
            float lx = fmaxf(ax, mb.x), ly = fmaxf(ay, mb.y);
            float rx = fminf(az, mb.z), ry = fminf(aw, mb.w);
            float inter = fmaxf(rx - lx, 0.f) * fmaxf(ry - ly, 0.f);
            float iou = inter / (areaA + areaM - inter + 1e-7f);
            bool sbit = (lane > i) && (lane < n) && (iou > 0.45f);
            supp |= __ballot_sync(0xFFFFFFFFu, sbit);
        }
        if (lane < n && !((supp >> lane) & 1u)) g_keepB[b * TPAD + myr] = 1;
    } else if (n > 32) {
        int words = (n + 31) >> 5;
        for (int w = lane; w < words; w += 32) ssupp[warp][w] = 0;
        __syncwarp();
        for (int i = 0; i < n; i++) {
            if ((ssupp[warp][i >> 5] >> (i & 31)) & 1u) continue;
            float4 a = g_nmsbox[b * TPAD + slist[warp][i]];
            float areaA = (a.z - a.x) * (a.w - a.y);
            for (int w = i >> 5; w < words; w++) {
                int j = w * 32 + lane;
                bool sbit = false;
                if (j > i && j < n) {
                    float4 bb = g_nmsbox[b * TPAD + slist[warp][j]];
                    float areaB = (bb.z - bb.x) * (bb.w - bb.y);
                    float lx = fmaxf(a.x, bb.x), ly = fmaxf(a.y, bb.y);
                    float rx = fminf(a.z, bb.z), ry = fminf(a.w, bb.w);
                    float inter = fmaxf(rx - lx, 0.f) * fmaxf(ry - ly, 0.f);
                    float iou = inter / (areaA + areaB - inter + 1e-7f);
                    sbit = iou > 0.45f;
                }
                uint32_t bal = __ballot_sync(0xFFFFFFFFu, sbit);
                if (lane == 0 && bal) ssupp[warp][w] |= bal;
                __syncwarp();
            }
        }
        for (int j = lane; j < n; j += 32)
            if (!((ssupp[warp][j >> 5] >> (j & 31)) & 1u))
                g_keepB[b * TPAD + slist[warp][j]] = 1;
    }

    // ---- last block of this image performs compaction + output ----
    __threadfence();
    __syncthreads();
    if (tid == 0) s_last = (atomicAdd(&g_done[b], 1u) == gridDim.x - 1);
    __syncthreads();
    if (!s_last) return;

    float* ob = out + (size_t)b * (MAXDET * 6);
    for (int i = tid; i < MAXDET * 6; i += 256) ob[i] = 0.0f;

    uint8_t kb[6];
#pragma unroll
    for (int s = 0; s < 6; s++)
        kb[s] = g_keepB[b * TPAD + (warp * 6 + s) * 32 + lane];
#pragma unroll
    for (int s = 0; s < 6; s++) {
        uint32_t word = __ballot_sync(0xFFFFFFFFu, kb[s] != 0);
        if (lane == 0) keepw[warp * 6 + s] = word;
    }
    __syncthreads();
    if (tid == 0) {
        uint32_t s = 0;
        for (int w = 0; w < NWP; w++) { wpre[w] = s; s += __popc(keepw[w]); }
    }
    __syncthreads();
    for (int r = tid; r < KTOP; r += 256) {
        int w = r >> 5;
        uint32_t word = keepw[w];
        uint32_t bit = 1u << (r & 31);
        if (word & bit) {
            uint32_t rank = wpre[w] + __popc(word & (bit - 1u));
            if (rank < MAXDET) {
                float4 bx = g_selbox[b * TPAD + r];
                float* o = ob + rank * 6;
                o[0] = bx.x; o[1] = bx.y; o[2] = bx.z; o[3] = bx.w;
                o[4] = g_selscore[b * TPAD + r];
                o[5] = g_selcls[b * TPAD + r];
            }
        }
    }
}

// ---------------- launch ----------------
extern "C" void kernel_launch(void* const* d_in, const int* in_sizes, int n_in,
                              void* d_out, int out_size) {
    const float* pred = (const float*)d_in[0];
    float* out = (float*)d_out;
    k_score<<<dim3((AA + 255) / 256, BB), 256>>>(pred);
    k_topk<<<BB, 1024>>>(pred);
    k_nms<<<dim3(10, BB), 256>>>(out);
}